// round 8
// baseline (speedup 1.0000x reference)
#include <cuda_runtime.h>
#include <cstddef>

// STFT via four-step FFT (1024 = 32x32), real-pair packed, 2 lanes per 32-pt FFT.
// Round-8: input staged once per block via coalesced float4 -> padded smem;
// stage A reads from smem (conflict-free). mag buffer unions with input buffer.
//
// Output: magnitude (32, 513, 1025) fp32.

#define NS        524288
#define BATCHES   32
#define NFRAMES   1025
#define CUTOFF    513
#define HOP       512
#define FPB       16        // frames per block (8 groups x 2 frames)
#define THREADS   512
#define NGROUP    8
#define FULLMASK  0xFFFFFFFFu

#define SPAN      9216      // samples staged per block: 16*512 + 1024
#define SPAD      9504      // padded floats: +16 per 512
#define PAD(n)    ((n) + 16 * ((n) >> 9))

// shared layout (floats):
//  sbuf[SPAD] (UNION with mag2[513*9 float2])  |  8 group tiles of 32*33 float2
#define TILE_F2   (32*33)                       // 1056 float2 per group
#define SM_FLOATS (SPAD + NGROUP * TILE_F2 * 2) // 9504 + 16896 = 26400
#define SMEM_BYTES (SM_FLOATS * 4)              // 105600 B -> 2 blocks/SM

__device__ __forceinline__ constexpr int brev4(int x) {
    return ((x & 1) << 3) | ((x & 2) << 1) | ((x & 4) >> 1) | ((x & 8) >> 3);
}

__device__ __forceinline__ float sqrt_fast(float x) {
    float r;
    asm("sqrt.approx.f32 %0, %1;" : "=f"(r) : "f"(x));
    return r;
}

__device__ __forceinline__ void cmul(float& dr, float& di,
                                     float ar, float ai, float br, float bi) {
    dr = ar * br - ai * bi;
    di = ar * bi + ai * br;
}

// DIF radix-2 16-point FFT, natural input order, bit-reversed output:
// after the call, a[r] = X[brev4(r)].
__device__ __forceinline__ void fft16(float ar[16], float ai[16]) {
    constexpr float TC[8] = { 1.0f, 0.9238795325f, 0.7071067812f, 0.3826834324f,
                              0.0f, -0.3826834324f, -0.7071067812f, -0.9238795325f };
    constexpr float TS[8] = { 0.0f, 0.3826834324f, 0.7071067812f, 0.9238795325f,
                              1.0f, 0.9238795325f, 0.7071067812f, 0.3826834324f };
#pragma unroll
    for (int ls = 4; ls >= 1; --ls) {
        const int half = 1 << (ls - 1);
        const int nblk = 1 << (4 - ls);
        const int step = 1 << (4 - ls);
#pragma unroll
        for (int blk = 0; blk < nblk; ++blk) {
#pragma unroll
            for (int j = 0; j < half; ++j) {
                const int i0 = (blk << ls) + j;
                const int i1 = i0 + half;
                float ur = ar[i0] + ar[i1];
                float ui = ai[i0] + ai[i1];
                float vr = ar[i0] - ar[i1];
                float vi = ai[i0] - ai[i1];
                const float c = TC[j * step];
                const float s = TS[j * step];
                ar[i0] = ur; ai[i0] = ui;
                ar[i1] = vr * c + vi * s;     // (vr + i vi) * (c - i s)
                ai[i1] = vi * c - vr * s;
            }
        }
    }
}

// Cross-lane radix-2 stage of a 32-pt FFT split over lane pairs (lane, lane^16).
__device__ __forceinline__ void cross32(float ar[16], float ai[16], int h) {
    constexpr float C32[16] = {
        1.0f, 0.9807852804f, 0.9238795325f, 0.8314696123f,
        0.7071067812f, 0.5555702330f, 0.3826834324f, 0.1950903220f,
        0.0f, -0.1950903220f, -0.3826834324f, -0.5555702330f,
        -0.7071067812f, -0.8314696123f, -0.9238795325f, -0.9807852804f };
    constexpr float S32[16] = {
        0.0f, 0.1950903220f, 0.3826834324f, 0.5555702330f,
        0.7071067812f, 0.8314696123f, 0.9238795325f, 0.9807852804f,
        1.0f, 0.9807852804f, 0.9238795325f, 0.8314696123f,
        0.7071067812f, 0.5555702330f, 0.3826834324f, 0.1950903220f };
    const bool hi = (h != 0);
#pragma unroll
    for (int j = 0; j < 16; ++j) {
        const float orr = __shfl_xor_sync(FULLMASK, ar[j], 16);
        const float oii = __shfl_xor_sync(FULLMASK, ai[j], 16);
        const float dr = hi ? (orr - ar[j]) : (ar[j] + orr);
        const float di = hi ? (oii - ai[j]) : (ai[j] + oii);
        const float c  = hi ? C32[j] : 1.0f;
        const float s  = hi ? S32[j] : 0.0f;
        ar[j] = dr * c + di * s;
        ai[j] = di * c - dr * s;
    }
}

__device__ __forceinline__ int reflect_idx(int idx) {
    idx = (idx < 0) ? -idx : idx;
    idx = (idx >= NS) ? (2 * NS - 2 - idx) : idx;
    return idx;
}

__global__ void __launch_bounds__(THREADS, 2)
stft_kernel(const float* __restrict__ x, float* __restrict__ out) {
    extern __shared__ float sm[];
    float*  sbuf  = sm;                               // staged input (padded)
    float2* tiles = (float2*)(sm + SPAD);             // group transpose tiles
    float2* mag2  = (float2*)sm;                      // UNION with sbuf (sbuf dead first)

    const int tid  = threadIdx.x;
    const int warp = tid >> 5;
    const int lane = tid & 31;
    const int l4   = lane & 15;
    const int h    = lane >> 4;          // half-bit within the lane pair
    const int grp  = warp >> 1;          // 2-warp group = one frame pair
    const int wsub = warp & 1;
    float2* tile = tiles + grp * TILE_F2;

    const int b  = blockIdx.y;
    const int t0 = blockIdx.x * FPB;
    const float* __restrict__ xb = x + (size_t)b * NS;

    // ---- stage 0: cooperative input staging into padded smem.
    const int gstart = t0 * HOP - 512;
    if (gstart >= 0 && gstart + SPAN <= NS) {
        const float4* __restrict__ src = (const float4*)(xb + gstart);
#pragma unroll
        for (int it = 0; it < SPAN / 4 / THREADS + 1; ++it) {
            const int i = tid + it * THREADS;
            if (i < SPAN / 4) {
                const float4 v = __ldg(src + i);
                const int n = 4 * i;
                sbuf[PAD(n)]     = v.x;
                sbuf[PAD(n + 1)] = v.y;
                sbuf[PAD(n + 2)] = v.z;
                sbuf[PAD(n + 3)] = v.w;
            }
        }
    } else {
        for (int n = tid; n < SPAN; n += THREADS)
            sbuf[PAD(n)] = __ldg(xb + reflect_idx(gstart + n));
    }
    __syncthreads();

    const int t = t0 + grp * 2;
    const bool active = (t < NFRAMES);

    float ar[16], ai[16];
    const int n2 = l4 + 16 * wsub;

    // One trig call per lane: c0 = cos(pi*n2/512), s0 = sin(pi*n2/512)
    float s0, c0;
    sincospif((float)n2 * (1.0f / 512.0f), &s0, &c0);

    if (active) {
        // ---- stage A loads: window via recurrence, samples from smem.
        // w[n] = 0.5 - 0.5*(-1)^h * cos(pi*j/16 + pi*n2/512), n = 512h + 32j + n2
        const int lbase = grp * 1024 + 512 * h + n2;
        const float Cs = 0.9807852804f, Ss = 0.1950903220f;  // rot by pi/16
        const float wsgn = h ? 0.5f : -0.5f;
        float wcc = c0, wss = s0;
#pragma unroll
        for (int j = 0; j < 16; ++j) {
            const int nl = lbase + 32 * j;
            const float w = 0.5f + wsgn * wcc;
            ar[j] = sbuf[PAD(nl)] * w;          // frame t   (real part)
            ai[j] = sbuf[PAD(nl + 512)] * w;    // frame t+1 (imag part)
            const float nc = wcc * Cs - wss * Ss;
            wss = wss * Cs + wcc * Ss;
            wcc = nc;
        }
    }
    __syncthreads();   // all sbuf reads done; mag2 (union) may now be written

    if (active) {
        cross32(ar, ai, h);
        fft16(ar, ai);     // reg r holds A[n2, k1 = 2*brev4(r) + h]

        // ---- twiddle by W1024^{n2*k1}, k1 = 2m + h, m = 4q + p.
        // Seeds W^{n2*(2p+h)} from one sincospif by complex squaring; step W^8n2.
        float w2r, w2i, w4r, w4i, w6r, w6i, w8r, w8i;
        cmul(w2r, w2i, c0, -s0, c0, -s0);          // W^2n2
        cmul(w4r, w4i, w2r, w2i, w2r, w2i);        // W^4n2
        cmul(w6r, w6i, w2r, w2i, w4r, w4i);        // W^6n2
        cmul(w8r, w8i, w4r, w4i, w4r, w4i);        // W^8n2
        const float br = h ? c0 : 1.0f;
        const float bi = h ? -s0 : 0.0f;
        float cr[4], ci[4];
        cr[0] = br;  ci[0] = bi;
        cmul(cr[1], ci[1], br, bi, w2r, w2i);
        cmul(cr[2], ci[2], br, bi, w4r, w4i);
        cmul(cr[3], ci[3], br, bi, w6r, w6i);

#pragma unroll
        for (int q = 0; q < 4; ++q) {
#pragma unroll
            for (int p = 0; p < 4; ++p) {
                const int m  = 4 * q + p;
                const int r  = brev4(m);
                const int k1 = 2 * m + h;
                float vr, vi;
                cmul(vr, vi, ar[r], ai[r], cr[p], ci[p]);
                tile[k1 * 33 + n2] = make_float2(vr, vi);   // STS.64
                if (q < 3) {
                    float nr, ni;
                    cmul(nr, ni, cr[p], ci[p], w8r, w8i);
                    cr[p] = nr; ci[p] = ni;
                }
            }
        }

        // group barrier: order tile stores before tile loads (2 warps, id grp+1)
        asm volatile("bar.sync %0, %1;" :: "r"(grp + 1), "r"(64) : "memory");

        // ---- stage B: k1 -> lane map keeps k1 and 32-k1 in the SAME warp.
        int k1;
        if (wsub == 0) {
            if (l4 == 0)      k1 = 0;
            else if (l4 == 1) k1 = 16;
            else {
                const int p = l4 >> 1;
                k1 = (l4 & 1) ? (32 - p) : p;
            }
        } else {
            const int p = 8 + (l4 >> 1);
            k1 = (l4 & 1) ? (32 - p) : p;
        }

#pragma unroll
        for (int j = 0; j < 16; ++j) {
            const float2 v = tile[k1 * 33 + 16 * h + j];    // LDS.64
            ar[j] = v.x;
            ai[j] = v.y;
        }
        cross32(ar, ai, h);
        fft16(ar, ai);     // reg r holds Z[k1 + 32*(2*brev4(r) + h)]

        // ---- conjugate-symmetry unpack + magnitudes.
        // partner of even reg r at reg 15-r of: generic lane^17; k1==16 lane^16
        // (warp0,l4==1); k1==0 same lane (warp0,l4==0; h==0 via TBL).
        const bool k1zero = (wsub == 0) && (l4 == 0);
        const bool k1mid  = (wsub == 0) && (l4 == 1);
        const int msk = k1zero ? 0 : (k1mid ? 16 : 17);
        constexpr int TBL[8] = { 0, 3, 7, 5, 15, 13, 11, 9 };
#pragma unroll
        for (int ri = 0; ri < 8; ++ri) {
            const int r = 2 * ri;
            float qr = __shfl_xor_sync(FULLMASK, ar[15 - r], msk);
            float qi = __shfl_xor_sync(FULLMASK, ai[15 - r], msk);
            if (k1zero && h == 0) { qr = ar[TBL[ri]]; qi = ai[TBL[ri]]; }
            const float zr = ar[r], zi = ai[r];
            const float e0r = zr + qr, e0i = zi - qi;   // X_t[k]     * 2
            const float e1r = zr - qr, e1i = zi + qi;   // X_{t+1}[k] * 2i
            const float m0 = 0.5f * sqrt_fast(e0r * e0r + e0i * e0i);
            const float m1 = 0.5f * sqrt_fast(e1r * e1r + e1i * e1i);
            const int k2 = 2 * brev4(r) + h;
            const int k  = k1 + 32 * k2;
            mag2[k * 9 + grp] = make_float2(m0, m1);    // STS.64
        }
        if (k1zero && h == 0) {   // k = 512 lives at reg 1 (k2 = 16)
            mag2[512 * 9 + grp] = make_float2(fabsf(ar[1]), fabsf(ai[1]));
        }
    }
    __syncthreads();

    // ---- writeback: thread -> (k, group); LDS.64 then two STG.32
    const size_t obase = (size_t)b * CUTOFF * NFRAMES;
    for (int i = tid; i < CUTOFF * NGROUP; i += THREADS) {   // 513*8 = 4104
        const int k = i >> 3;
        const int g = i & 7;
        const float2 v = mag2[k * 9 + g];
        const int tt = t0 + 2 * g;
        float* orow = out + obase + (size_t)k * NFRAMES;
        if (tt < NFRAMES)     orow[tt] = v.x;
        if (tt + 1 < NFRAMES) orow[tt + 1] = v.y;
    }
}

extern "C" void kernel_launch(void* const* d_in, const int* in_sizes, int n_in,
                              void* d_out, int out_size) {
    const float* x = (const float*)d_in[0];
    // d_in[1] = forward_basis: identical to our windowed DFT; unused.
    float* out = (float*)d_out;

    cudaFuncSetAttribute(stft_kernel,
                         cudaFuncAttributeMaxDynamicSharedMemorySize, SMEM_BYTES);

    dim3 grid((NFRAMES + FPB - 1) / FPB, BATCHES);
    stft_kernel<<<grid, THREADS, SMEM_BYTES>>>(x, out);
}

// round 9
// speedup vs baseline: 1.0740x; 1.0740x over previous
#include <cuda_runtime.h>
#include <cstddef>

// STFT via four-step FFT (1024 = 32x32), real-pair packed, 2 lanes per 32-pt FFT.
// Round-9: 256 threads / 128-reg budget so the compiler can BATCH shuffles and
// global loads (latency-exposure theory); cross32 pre-issues all shuffles;
// stride-34 tile kills the h-pair bank conflict.
//
// Output: magnitude (32, 513, 1025) fp32.

#define NS        524288
#define BATCHES   32
#define NFRAMES   1025
#define CUTOFF    513
#define HOP       512
#define FPB       8         // frames per block (4 groups x 2 frames)
#define THREADS   256
#define NGROUP    4
#define FULLMASK  0xFFFFFFFFu

// shared layout (float2 units): 4 group tiles of 32*34 | mag2[513*5]
#define TILE_F2   (32*34)                       // 1088 float2 per group
#define SM_MAG2   (NGROUP * TILE_F2)            // 4352
#define MAGSTRIDE (NGROUP + 1)                  // 5
#define SM_F2     (SM_MAG2 + CUTOFF * MAGSTRIDE)   // 6917
#define SMEM_BYTES (SM_F2 * 8)                  // 55336 B -> 2 blocks/SM

__device__ __forceinline__ constexpr int brev4(int x) {
    return ((x & 1) << 3) | ((x & 2) << 1) | ((x & 4) >> 1) | ((x & 8) >> 3);
}

__device__ __forceinline__ float sqrt_fast(float x) {
    float r;
    asm("sqrt.approx.f32 %0, %1;" : "=f"(r) : "f"(x));
    return r;
}

__device__ __forceinline__ void cmul(float& dr, float& di,
                                     float ar, float ai, float br, float bi) {
    dr = ar * br - ai * bi;
    di = ar * bi + ai * br;
}

// DIF radix-2 16-point FFT, natural input order, bit-reversed output.
__device__ __forceinline__ void fft16(float ar[16], float ai[16]) {
    constexpr float TC[8] = { 1.0f, 0.9238795325f, 0.7071067812f, 0.3826834324f,
                              0.0f, -0.3826834324f, -0.7071067812f, -0.9238795325f };
    constexpr float TS[8] = { 0.0f, 0.3826834324f, 0.7071067812f, 0.9238795325f,
                              1.0f, 0.9238795325f, 0.7071067812f, 0.3826834324f };
#pragma unroll
    for (int ls = 4; ls >= 1; --ls) {
        const int half = 1 << (ls - 1);
        const int nblk = 1 << (4 - ls);
        const int step = 1 << (4 - ls);
#pragma unroll
        for (int blk = 0; blk < nblk; ++blk) {
#pragma unroll
            for (int j = 0; j < half; ++j) {
                const int i0 = (blk << ls) + j;
                const int i1 = i0 + half;
                float ur = ar[i0] + ar[i1];
                float ui = ai[i0] + ai[i1];
                float vr = ar[i0] - ar[i1];
                float vi = ai[i0] - ai[i1];
                const float c = TC[j * step];
                const float s = TS[j * step];
                ar[i0] = ur; ai[i0] = ui;
                ar[i1] = vr * c + vi * s;     // (vr + i vi) * (c - i s)
                ai[i1] = vi * c - vr * s;
            }
        }
    }
}

// Cross-lane radix-2 stage of a 32-pt FFT split over lane pairs (lane, lane^16).
// BATCHED: all 32 shuffles issued before any arithmetic (needs 32 spare regs).
__device__ __forceinline__ void cross32(float ar[16], float ai[16], int h) {
    constexpr float C32[16] = {
        1.0f, 0.9807852804f, 0.9238795325f, 0.8314696123f,
        0.7071067812f, 0.5555702330f, 0.3826834324f, 0.1950903220f,
        0.0f, -0.1950903220f, -0.3826834324f, -0.5555702330f,
        -0.7071067812f, -0.8314696123f, -0.9238795325f, -0.9807852804f };
    constexpr float S32[16] = {
        0.0f, 0.1950903220f, 0.3826834324f, 0.5555702330f,
        0.7071067812f, 0.8314696123f, 0.9238795325f, 0.9807852804f,
        1.0f, 0.9807852804f, 0.9238795325f, 0.8314696123f,
        0.7071067812f, 0.5555702330f, 0.3826834324f, 0.1950903220f };
    float br_[16], bi_[16];
#pragma unroll
    for (int j = 0; j < 16; ++j) {
        br_[j] = __shfl_xor_sync(FULLMASK, ar[j], 16);
        bi_[j] = __shfl_xor_sync(FULLMASK, ai[j], 16);
    }
    const bool hi = (h != 0);
#pragma unroll
    for (int j = 0; j < 16; ++j) {
        const float dr = hi ? (br_[j] - ar[j]) : (ar[j] + br_[j]);
        const float di = hi ? (bi_[j] - ai[j]) : (ai[j] + bi_[j]);
        const float c  = hi ? C32[j] : 1.0f;
        const float s  = hi ? S32[j] : 0.0f;
        ar[j] = dr * c + di * s;
        ai[j] = di * c - dr * s;
    }
}

__device__ __forceinline__ int reflect_idx(int idx) {
    idx = (idx < 0) ? -idx : idx;
    idx = (idx >= NS) ? (2 * NS - 2 - idx) : idx;
    return idx;
}

__global__ void __launch_bounds__(THREADS, 2)
stft_kernel(const float* __restrict__ x, float* __restrict__ out) {
    extern __shared__ float2 sm2[];
    float2* mag2 = sm2 + SM_MAG2;

    const int tid  = threadIdx.x;
    const int warp = tid >> 5;
    const int lane = tid & 31;
    const int l4   = lane & 15;
    const int h    = lane >> 4;          // half-bit within the lane pair
    const int grp  = warp >> 1;          // 2-warp group = one frame pair
    const int wsub = warp & 1;
    float2* tile = sm2 + grp * TILE_F2;

    const int b  = blockIdx.y;
    const int t0 = blockIdx.x * FPB;
    const float* __restrict__ xb = x + (size_t)b * NS;

    const int t = t0 + grp * 2;
    const bool active = (t < NFRAMES);

    float ar[16], ai[16];
    const int n2 = l4 + 16 * wsub;

    // One trig call per lane: c0 = cos(pi*n2/512), s0 = sin(pi*n2/512)
    float s0, c0;
    sincospif((float)n2 * (1.0f / 512.0f), &s0, &c0);

    if (active) {
        // ---- stage A: batched global loads, window via recurrence.
        // w[n] = 0.5 - 0.5*(-1)^h * cos(pi*j/16 + pi*n2/512), n = 512h + 32j + n2
        const int base = t * HOP - 512 + 512 * h + n2;
        float xr[16], xi[16];
#pragma unroll
        for (int j = 0; j < 16; ++j) {
            xr[j] = __ldg(xb + reflect_idx(base + 32 * j));
            xi[j] = __ldg(xb + reflect_idx(base + 32 * j + 512));
        }
        const float Cs = 0.9807852804f, Ss = 0.1950903220f;  // rot by pi/16
        const float wsgn = h ? 0.5f : -0.5f;
        float wcc = c0, wss = s0;
#pragma unroll
        for (int j = 0; j < 16; ++j) {
            const float w = 0.5f + wsgn * wcc;
            ar[j] = xr[j] * w;            // frame t   (real part)
            ai[j] = xi[j] * w;            // frame t+1 (imag part)
            const float nc = wcc * Cs - wss * Ss;
            wss = wss * Cs + wcc * Ss;
            wcc = nc;
        }
        cross32(ar, ai, h);
        fft16(ar, ai);     // reg r holds A[n2, k1 = 2*brev4(r) + h]

        // ---- twiddle by W1024^{n2*k1}, k1 = 2m + h, m = 4q + p.
        // Seeds W^{n2*(2p+h)} from one sincospif by complex squaring; step W^8n2.
        float w2r, w2i, w4r, w4i, w6r, w6i, w8r, w8i;
        cmul(w2r, w2i, c0, -s0, c0, -s0);          // W^2n2
        cmul(w4r, w4i, w2r, w2i, w2r, w2i);        // W^4n2
        cmul(w6r, w6i, w2r, w2i, w4r, w4i);        // W^6n2
        cmul(w8r, w8i, w4r, w4i, w4r, w4i);        // W^8n2
        const float br = h ? c0 : 1.0f;
        const float bi = h ? -s0 : 0.0f;
        float cr[4], ci[4];
        cr[0] = br;  ci[0] = bi;
        cmul(cr[1], ci[1], br, bi, w2r, w2i);
        cmul(cr[2], ci[2], br, bi, w4r, w4i);
        cmul(cr[3], ci[3], br, bi, w6r, w6i);

        // tile column for this lane's n2 (stride-34 rows, +1 pad at col 16)
        const int colA = n2 + (n2 >> 4);
#pragma unroll
        for (int q = 0; q < 4; ++q) {
#pragma unroll
            for (int p = 0; p < 4; ++p) {
                const int m  = 4 * q + p;
                const int r  = brev4(m);
                const int k1 = 2 * m + h;
                float vr, vi;
                cmul(vr, vi, ar[r], ai[r], cr[p], ci[p]);
                tile[k1 * 34 + colA] = make_float2(vr, vi);   // STS.64
                if (q < 3) {
                    float nr, ni;
                    cmul(nr, ni, cr[p], ci[p], w8r, w8i);
                    cr[p] = nr; ci[p] = ni;
                }
            }
        }

        // group barrier: order tile stores before tile loads (2 warps, id grp+1)
        asm volatile("bar.sync %0, %1;" :: "r"(grp + 1), "r"(64) : "memory");

        // ---- stage B: k1 -> lane map keeps k1 and 32-k1 in the SAME warp.
        int k1;
        if (wsub == 0) {
            if (l4 == 0)      k1 = 0;
            else if (l4 == 1) k1 = 16;
            else {
                const int p = l4 >> 1;
                k1 = (l4 & 1) ? (32 - p) : p;
            }
        } else {
            const int p = 8 + (l4 >> 1);
            k1 = (l4 & 1) ? (32 - p) : p;
        }

        // read col = 17h + j  (n2v = 16h + j); h halves now 34 words apart -> no conflict
        const float2* trow = tile + k1 * 34 + 17 * h;
#pragma unroll
        for (int j = 0; j < 16; ++j) {
            const float2 v = trow[j];       // LDS.64, batched
            ar[j] = v.x;
            ai[j] = v.y;
        }
        cross32(ar, ai, h);
        fft16(ar, ai);     // reg r holds Z[k1 + 32*(2*brev4(r) + h)]

        // ---- conjugate-symmetry unpack + magnitudes.
        // partner of even reg r at reg 15-r of: generic lane^17; k1==16 lane^16
        // (warp0,l4==1); k1==0 same lane (warp0,l4==0; h==0 via TBL).
        const bool k1zero = (wsub == 0) && (l4 == 0);
        const bool k1mid  = (wsub == 0) && (l4 == 1);
        const int msk = k1zero ? 0 : (k1mid ? 16 : 17);
        constexpr int TBL[8] = { 0, 3, 7, 5, 15, 13, 11, 9 };
        float qr_[8], qi_[8];
#pragma unroll
        for (int ri = 0; ri < 8; ++ri) {        // batch all unpack shuffles
            qr_[ri] = __shfl_xor_sync(FULLMASK, ar[15 - 2 * ri], msk);
            qi_[ri] = __shfl_xor_sync(FULLMASK, ai[15 - 2 * ri], msk);
        }
#pragma unroll
        for (int ri = 0; ri < 8; ++ri) {
            const int r = 2 * ri;
            float qr = qr_[ri], qi = qi_[ri];
            if (k1zero && h == 0) { qr = ar[TBL[ri]]; qi = ai[TBL[ri]]; }
            const float zr = ar[r], zi = ai[r];
            const float e0r = zr + qr, e0i = zi - qi;   // X_t[k]     * 2
            const float e1r = zr - qr, e1i = zi + qi;   // X_{t+1}[k] * 2i
            const float m0 = 0.5f * sqrt_fast(e0r * e0r + e0i * e0i);
            const float m1 = 0.5f * sqrt_fast(e1r * e1r + e1i * e1i);
            const int k2 = 2 * brev4(r) + h;
            const int k  = k1 + 32 * k2;
            mag2[k * MAGSTRIDE + grp] = make_float2(m0, m1);    // STS.64
        }
        if (k1zero && h == 0) {   // k = 512 lives at reg 1 (k2 = 16)
            mag2[512 * MAGSTRIDE + grp] = make_float2(fabsf(ar[1]), fabsf(ai[1]));
        }
    }
    __syncthreads();

    // ---- writeback: thread -> (k, group); LDS.64 then two STG.32
    const size_t obase = (size_t)b * CUTOFF * NFRAMES;
    for (int i = tid; i < CUTOFF * NGROUP; i += THREADS) {   // 513*4 = 2052
        const int k = i >> 2;
        const int g = i & 3;
        const float2 v = mag2[k * MAGSTRIDE + g];
        const int tt = t0 + 2 * g;
        float* orow = out + obase + (size_t)k * NFRAMES;
        if (tt < NFRAMES)     orow[tt] = v.x;
        if (tt + 1 < NFRAMES) orow[tt + 1] = v.y;
    }
}

extern "C" void kernel_launch(void* const* d_in, const int* in_sizes, int n_in,
                              void* d_out, int out_size) {
    const float* x = (const float*)d_in[0];
    // d_in[1] = forward_basis: identical to our windowed DFT; unused.
    float* out = (float*)d_out;

    cudaFuncSetAttribute(stft_kernel,
                         cudaFuncAttributeMaxDynamicSharedMemorySize, SMEM_BYTES);

    dim3 grid((NFRAMES + FPB - 1) / FPB, BATCHES);
    stft_kernel<<<grid, THREADS, SMEM_BYTES>>>(x, out);
}

// round 10
// speedup vs baseline: 1.2231x; 1.1388x over previous
#include <cuda_runtime.h>
#include <cstddef>

// STFT via four-step FFT (1024 = 32x32), real-pair packed, 2 lanes per 32-pt FFT.
// Round-10: shuffle elimination. Stage-A cross butterfly done from overlapping
// global loads (partner sample n+512 of frame t == sample n of frame t+1);
// stage-B cross butterfly via dual LDS reads. Only the 16 unpack shuffles remain.
// 3 blocks/SM (85-reg cap) for latency hiding.
//
// Output: magnitude (32, 513, 1025) fp32.

#define NS        524288
#define BATCHES   32
#define NFRAMES   1025
#define CUTOFF    513
#define HOP       512
#define FPB       8         // frames per block (4 groups x 2 frames)
#define THREADS   256
#define NGROUP    4
#define FULLMASK  0xFFFFFFFFu

// shared layout (float2 units): 4 group tiles of 32*35 | mag2[513*5]
#define TSTRIDE   35                            // row stride (float2) -> conflict-free
#define TILE_F2   (32*TSTRIDE)                  // 1120 float2 per group
#define SM_MAG2   (NGROUP * TILE_F2)            // 4480
#define MAGSTRIDE (NGROUP + 1)                  // 5
#define SM_F2     (SM_MAG2 + CUTOFF * MAGSTRIDE)   // 7045
#define SMEM_BYTES (SM_F2 * 8)                  // 56360 B -> 3 blocks/SM

__device__ __forceinline__ constexpr int brev4(int x) {
    return ((x & 1) << 3) | ((x & 2) << 1) | ((x & 4) >> 1) | ((x & 8) >> 3);
}

__device__ __forceinline__ float sqrt_fast(float x) {
    float r;
    asm("sqrt.approx.f32 %0, %1;" : "=f"(r) : "f"(x));
    return r;
}

__device__ __forceinline__ void cmul(float& dr, float& di,
                                     float ar, float ai, float br, float bi) {
    dr = ar * br - ai * bi;
    di = ar * bi + ai * br;
}

// W32^j = C32[j] - i*S32[j]
__device__ __constant__ const float C32c[16] = {
    1.0f, 0.9807852804f, 0.9238795325f, 0.8314696123f,
    0.7071067812f, 0.5555702330f, 0.3826834324f, 0.1950903220f,
    0.0f, -0.1950903220f, -0.3826834324f, -0.5555702330f,
    -0.7071067812f, -0.8314696123f, -0.9238795325f, -0.9807852804f };
__device__ __constant__ const float S32c[16] = {
    0.0f, 0.1950903220f, 0.3826834324f, 0.5555702330f,
    0.7071067812f, 0.8314696123f, 0.9238795325f, 0.9807852804f,
    1.0f, 0.9807852804f, 0.9238795325f, 0.8314696123f,
    0.7071067812f, 0.5555702330f, 0.3826834324f, 0.1950903220f };

// DIF radix-2 16-point FFT, natural input order, bit-reversed output.
__device__ __forceinline__ void fft16(float ar[16], float ai[16]) {
    constexpr float TC[8] = { 1.0f, 0.9238795325f, 0.7071067812f, 0.3826834324f,
                              0.0f, -0.3826834324f, -0.7071067812f, -0.9238795325f };
    constexpr float TS[8] = { 0.0f, 0.3826834324f, 0.7071067812f, 0.9238795325f,
                              1.0f, 0.9238795325f, 0.7071067812f, 0.3826834324f };
#pragma unroll
    for (int ls = 4; ls >= 1; --ls) {
        const int half = 1 << (ls - 1);
        const int nblk = 1 << (4 - ls);
        const int step = 1 << (4 - ls);
#pragma unroll
        for (int blk = 0; blk < nblk; ++blk) {
#pragma unroll
            for (int j = 0; j < half; ++j) {
                const int i0 = (blk << ls) + j;
                const int i1 = i0 + half;
                float ur = ar[i0] + ar[i1];
                float ui = ai[i0] + ai[i1];
                float vr = ar[i0] - ar[i1];
                float vi = ai[i0] - ai[i1];
                const float c = TC[j * step];
                const float s = TS[j * step];
                ar[i0] = ur; ai[i0] = ui;
                ar[i1] = vr * c + vi * s;     // (vr + i vi) * (c - i s)
                ai[i1] = vi * c - vr * s;
            }
        }
    }
}

__device__ __forceinline__ int reflect_idx(int idx) {
    idx = (idx < 0) ? -idx : idx;
    idx = (idx >= NS) ? (2 * NS - 2 - idx) : idx;
    return idx;
}

__global__ void __launch_bounds__(THREADS, 3)
stft_kernel(const float* __restrict__ x, float* __restrict__ out) {
    extern __shared__ float2 sm2[];
    float2* mag2 = sm2 + SM_MAG2;

    const int tid  = threadIdx.x;
    const int warp = tid >> 5;
    const int lane = tid & 31;
    const int l4   = lane & 15;
    const int h    = lane >> 4;          // half-bit within the lane pair
    const int grp  = warp >> 1;          // 2-warp group = one frame pair
    const int wsub = warp & 1;
    float2* tile = sm2 + grp * TILE_F2;

    const int b  = blockIdx.y;
    const int t0 = blockIdx.x * FPB;
    const float* __restrict__ xb = x + (size_t)b * NS;

    const int t = t0 + grp * 2;
    const bool active = (t < NFRAMES);

    float ar[16], ai[16];
    const int n2 = l4 + 16 * wsub;

    // One trig call per lane: c0 = cos(pi*n2/512), s0 = sin(pi*n2/512)
    float s0, c0;
    sincospif((float)n2 * (1.0f / 512.0f), &s0, &c0);

    if (active) {
        // ---- stage A: cross butterfly straight from overlapping loads.
        // Packed z[n] = w[n]*(X[n] + i*X[n+512]); butterfly partner z[n+512]
        // = w[n+512]*(X[n+512] + i*X[n+1024]). Both lanes of the h-pair load
        // the SAME three samples (h doesn't enter the address).
        const int gbase = t * HOP - 512 + n2;
        float X0[16], X1[16], X2[16];
#pragma unroll
        for (int j = 0; j < 16; ++j) {
            X0[j] = __ldg(xb + reflect_idx(gbase + 32 * j));
            X1[j] = __ldg(xb + reflect_idx(gbase + 32 * j + 512));
            X2[j] = __ldg(xb + reflect_idx(gbase + 32 * j + 1024));
        }
        // window: w[n] = 0.5 - 0.5*cos(pi*j/16 + pi*n2/512) ; w[n+512] = 0.5 + 0.5*cos(..)
        const float Cs = 0.9807852804f, Ss = 0.1950903220f;  // rot by pi/16
        float wcc = c0, wss = s0;
#pragma unroll
        for (int j = 0; j < 16; ++j) {
            const float wm = 0.5f - 0.5f * wcc;
            const float wp = 0.5f + 0.5f * wcc;
            const float z0r = wm * X0[j], z0i = wm * X1[j];
            const float z1r = wp * X1[j], z1i = wp * X2[j];
            if (h == 0) {                      // u = z0 + z1
                ar[j] = z0r + z1r;
                ai[j] = z0i + z1i;
            } else {                           // v = (z0 - z1) * W32^j
                const float dr = z0r - z1r;
                const float di = z0i - z1i;
                ar[j] = dr * C32c[j] + di * S32c[j];
                ai[j] = di * C32c[j] - dr * S32c[j];
            }
            const float nc = wcc * Cs - wss * Ss;
            wss = wss * Cs + wcc * Ss;
            wcc = nc;
        }
        fft16(ar, ai);     // reg r holds A[n2, k1 = 2*brev4(r) + h]

        // ---- twiddle by W1024^{n2*k1}, k1 = 2m + h, m = 4q + p.
        // Seeds W^{n2*(2p+h)} from one sincospif by complex squaring; step W^8n2.
        float w2r, w2i, w4r, w4i, w6r, w6i, w8r, w8i;
        cmul(w2r, w2i, c0, -s0, c0, -s0);          // W^2n2
        cmul(w4r, w4i, w2r, w2i, w2r, w2i);        // W^4n2
        cmul(w6r, w6i, w2r, w2i, w4r, w4i);        // W^6n2
        cmul(w8r, w8i, w4r, w4i, w4r, w4i);        // W^8n2
        const float br = h ? c0 : 1.0f;
        const float bi = h ? -s0 : 0.0f;
        float cr[4], ci[4];
        cr[0] = br;  ci[0] = bi;
        cmul(cr[1], ci[1], br, bi, w2r, w2i);
        cmul(cr[2], ci[2], br, bi, w4r, w4i);
        cmul(cr[3], ci[3], br, bi, w6r, w6i);

#pragma unroll
        for (int q = 0; q < 4; ++q) {
#pragma unroll
            for (int p = 0; p < 4; ++p) {
                const int m  = 4 * q + p;
                const int r  = brev4(m);
                const int k1 = 2 * m + h;
                float vr, vi;
                cmul(vr, vi, ar[r], ai[r], cr[p], ci[p]);
                tile[k1 * TSTRIDE + n2] = make_float2(vr, vi);   // STS.64
                if (q < 3) {
                    float nr, ni;
                    cmul(nr, ni, cr[p], ci[p], w8r, w8i);
                    cr[p] = nr; ci[p] = ni;
                }
            }
        }

        // group barrier: order tile stores before tile loads (2 warps, id grp+1)
        asm volatile("bar.sync %0, %1;" :: "r"(grp + 1), "r"(64) : "memory");

        // ---- stage B: k1 -> lane map keeps k1 and 32-k1 in the SAME warp.
        int k1;
        if (wsub == 0) {
            if (l4 == 0)      k1 = 0;
            else if (l4 == 1) k1 = 16;
            else {
                const int p = l4 >> 1;
                k1 = (l4 & 1) ? (32 - p) : p;
            }
        } else {
            const int p = 8 + (l4 >> 1);
            k1 = (l4 & 1) ? (32 - p) : p;
        }

        // dual LDS read of both halves + local cross butterfly (no shuffles)
        const float2* trow = tile + k1 * TSTRIDE;
        float b0r[16], b0i[16], b1r[16], b1i[16];
#pragma unroll
        for (int j = 0; j < 16; ++j) {
            const float2 a0 = trow[j];          // n2v = j
            const float2 a1 = trow[j + 16];     // n2v = j + 16
            b0r[j] = a0.x; b0i[j] = a0.y;
            b1r[j] = a1.x; b1i[j] = a1.y;
        }
#pragma unroll
        for (int j = 0; j < 16; ++j) {
            if (h == 0) {                       // u = a0 + a1
                ar[j] = b0r[j] + b1r[j];
                ai[j] = b0i[j] + b1i[j];
            } else {                            // v = (a0 - a1) * W32^j
                const float dr = b0r[j] - b1r[j];
                const float di = b0i[j] - b1i[j];
                ar[j] = dr * C32c[j] + di * S32c[j];
                ai[j] = di * C32c[j] - dr * S32c[j];
            }
        }
        fft16(ar, ai);     // reg r holds Z[k1 + 32*(2*brev4(r) + h)]

        // ---- conjugate-symmetry unpack + magnitudes.
        // partner of even reg r at reg 15-r of: generic lane^17; k1==16 lane^16
        // (warp0,l4==1); k1==0 same lane (warp0,l4==0; h==0 via TBL).
        const bool k1zero = (wsub == 0) && (l4 == 0);
        const bool k1mid  = (wsub == 0) && (l4 == 1);
        const int msk = k1zero ? 0 : (k1mid ? 16 : 17);
        constexpr int TBL[8] = { 0, 3, 7, 5, 15, 13, 11, 9 };
        float qr_[8], qi_[8];
#pragma unroll
        for (int ri = 0; ri < 8; ++ri) {        // batch all unpack shuffles
            qr_[ri] = __shfl_xor_sync(FULLMASK, ar[15 - 2 * ri], msk);
            qi_[ri] = __shfl_xor_sync(FULLMASK, ai[15 - 2 * ri], msk);
        }
#pragma unroll
        for (int ri = 0; ri < 8; ++ri) {
            const int r = 2 * ri;
            float qr = qr_[ri], qi = qi_[ri];
            if (k1zero && h == 0) { qr = ar[TBL[ri]]; qi = ai[TBL[ri]]; }
            const float zr = ar[r], zi = ai[r];
            const float e0r = zr + qr, e0i = zi - qi;   // X_t[k]     * 2
            const float e1r = zr - qr, e1i = zi + qi;   // X_{t+1}[k] * 2i
            const float m0 = 0.5f * sqrt_fast(e0r * e0r + e0i * e0i);
            const float m1 = 0.5f * sqrt_fast(e1r * e1r + e1i * e1i);
            const int k2 = 2 * brev4(r) + h;
            const int k  = k1 + 32 * k2;
            mag2[k * MAGSTRIDE + grp] = make_float2(m0, m1);    // STS.64
        }
        if (k1zero && h == 0) {   // k = 512 lives at reg 1 (k2 = 16)
            mag2[512 * MAGSTRIDE + grp] = make_float2(fabsf(ar[1]), fabsf(ai[1]));
        }
    }
    __syncthreads();

    // ---- writeback: thread -> (k, group); LDS.64 then two STG.32
    const size_t obase = (size_t)b * CUTOFF * NFRAMES;
    for (int i = tid; i < CUTOFF * NGROUP; i += THREADS) {   // 513*4 = 2052
        const int k = i >> 2;
        const int g = i & 3;
        const float2 v = mag2[k * MAGSTRIDE + g];
        const int tt = t0 + 2 * g;
        float* orow = out + obase + (size_t)k * NFRAMES;
        if (tt < NFRAMES)     orow[tt] = v.x;
        if (tt + 1 < NFRAMES) orow[tt + 1] = v.y;
    }
}

extern "C" void kernel_launch(void* const* d_in, const int* in_sizes, int n_in,
                              void* d_out, int out_size) {
    const float* x = (const float*)d_in[0];
    // d_in[1] = forward_basis: identical to our windowed DFT; unused.
    float* out = (float*)d_out;

    cudaFuncSetAttribute(stft_kernel,
                         cudaFuncAttributeMaxDynamicSharedMemorySize, SMEM_BYTES);

    dim3 grid((NFRAMES + FPB - 1) / FPB, BATCHES);
    stft_kernel<<<grid, THREADS, SMEM_BYTES>>>(x, out);
}

// round 11
// speedup vs baseline: 1.2348x; 1.0096x over previous
#include <cuda_runtime.h>
#include <cstddef>

// STFT via four-step FFT (1024 = 32x32), real-pair packed, 2 lanes per 32-pt FFT.
// Round-11: MIO slot diet + occupancy. Stage-B reads via LDS.128 (stride-34 tile),
// magnitude buffer UNIONed into the group tile (smem 35KB -> 4 blocks/SM),
// stage-A loads chunked to fit the 64-reg cap without spills.
//
// Output: magnitude (32, 513, 1025) fp32.

#define NS        524288
#define BATCHES   32
#define NFRAMES   1025
#define CUTOFF    513
#define HOP       512
#define FPB       8         // frames per block (4 groups x 2 frames)
#define THREADS   256
#define NGROUP    4
#define FULLMASK  0xFFFFFFFFu

// tile: 32 rows x stride 34 float2 (16B-aligned rows); group stride +8 float2
// so group bases differ by 8 (mod 16) 8B-banks for conflict-free writeback.
#define TSTRIDE   34
#define TILE_F2   (32*TSTRIDE)                  // 1088 float2
#define GSTRIDE   (TILE_F2 + 8)                 // 1096 float2
#define SM_F2     (NGROUP * GSTRIDE)            // 4384
#define SMEM_BYTES (SM_F2 * 8)                  // 35072 B -> 4+ blocks/SM

__device__ __forceinline__ constexpr int brev4(int x) {
    return ((x & 1) << 3) | ((x & 2) << 1) | ((x & 4) >> 1) | ((x & 8) >> 3);
}

__device__ __forceinline__ float sqrt_fast(float x) {
    float r;
    asm("sqrt.approx.f32 %0, %1;" : "=f"(r) : "f"(x));
    return r;
}

__device__ __forceinline__ void cmul(float& dr, float& di,
                                     float ar, float ai, float br, float bi) {
    dr = ar * br - ai * bi;
    di = ar * bi + ai * br;
}

// W32^j = C32[j] - i*S32[j]
__device__ __constant__ const float C32c[16] = {
    1.0f, 0.9807852804f, 0.9238795325f, 0.8314696123f,
    0.7071067812f, 0.5555702330f, 0.3826834324f, 0.1950903220f,
    0.0f, -0.1950903220f, -0.3826834324f, -0.5555702330f,
    -0.7071067812f, -0.8314696123f, -0.9238795325f, -0.9807852804f };
__device__ __constant__ const float S32c[16] = {
    0.0f, 0.1950903220f, 0.3826834324f, 0.5555702330f,
    0.7071067812f, 0.8314696123f, 0.9238795325f, 0.9807852804f,
    1.0f, 0.9807852804f, 0.9238795325f, 0.8314696123f,
    0.7071067812f, 0.5555702330f, 0.3826834324f, 0.1950903220f };

// DIF radix-2 16-point FFT, natural input order, bit-reversed output.
__device__ __forceinline__ void fft16(float ar[16], float ai[16]) {
    constexpr float TC[8] = { 1.0f, 0.9238795325f, 0.7071067812f, 0.3826834324f,
                              0.0f, -0.3826834324f, -0.7071067812f, -0.9238795325f };
    constexpr float TS[8] = { 0.0f, 0.3826834324f, 0.7071067812f, 0.9238795325f,
                              1.0f, 0.9238795325f, 0.7071067812f, 0.3826834324f };
#pragma unroll
    for (int ls = 4; ls >= 1; --ls) {
        const int half = 1 << (ls - 1);
        const int nblk = 1 << (4 - ls);
        const int step = 1 << (4 - ls);
#pragma unroll
        for (int blk = 0; blk < nblk; ++blk) {
#pragma unroll
            for (int j = 0; j < half; ++j) {
                const int i0 = (blk << ls) + j;
                const int i1 = i0 + half;
                float ur = ar[i0] + ar[i1];
                float ui = ai[i0] + ai[i1];
                float vr = ar[i0] - ar[i1];
                float vi = ai[i0] - ai[i1];
                const float c = TC[j * step];
                const float s = TS[j * step];
                ar[i0] = ur; ai[i0] = ui;
                ar[i1] = vr * c + vi * s;     // (vr + i vi) * (c - i s)
                ai[i1] = vi * c - vr * s;
            }
        }
    }
}

__device__ __forceinline__ int reflect_idx(int idx) {
    idx = (idx < 0) ? -idx : idx;
    idx = (idx >= NS) ? (2 * NS - 2 - idx) : idx;
    return idx;
}

__global__ void __launch_bounds__(THREADS, 4)
stft_kernel(const float* __restrict__ x, float* __restrict__ out) {
    extern __shared__ float2 sm2[];

    const int tid  = threadIdx.x;
    const int warp = tid >> 5;
    const int lane = tid & 31;
    const int l4   = lane & 15;
    const int h    = lane >> 4;          // half-bit within the lane pair
    const int grp  = warp >> 1;          // 2-warp group = one frame pair
    const int wsub = warp & 1;
    float2* tile = sm2 + grp * GSTRIDE;
    float2* magG = tile;                 // UNION: tile is dead after stage-B reads

    const int b  = blockIdx.y;
    const int t0 = blockIdx.x * FPB;
    const float* __restrict__ xb = x + (size_t)b * NS;

    const int t = t0 + grp * 2;
    const bool active = (t < NFRAMES);

    float ar[16], ai[16];
    const int n2 = l4 + 16 * wsub;

    // One trig call per lane: c0 = cos(pi*n2/512), s0 = sin(pi*n2/512)
    float s0, c0;
    sincospif((float)n2 * (1.0f / 512.0f), &s0, &c0);

    if (active) {
        // ---- stage A: cross butterfly straight from overlapping loads.
        // z[n] = w[n]*(X[n] + i*X[n+512]); partner z[n+512] = w[n+512]*(X[n+512]+i*X[n+1024]).
        // Chunked (2 x 8 j) so peak register pressure fits the 64-reg cap.
        const int gbase = t * HOP - 512 + n2;
        const float Cs = 0.9807852804f, Ss = 0.1950903220f;  // rot by pi/16
        float wcc = c0, wss = s0;
#pragma unroll
        for (int half8 = 0; half8 < 2; ++half8) {
            float X0[8], X1[8], X2[8];
#pragma unroll
            for (int jj = 0; jj < 8; ++jj) {
                const int off = 32 * (8 * half8 + jj);
                X0[jj] = __ldg(xb + reflect_idx(gbase + off));
                X1[jj] = __ldg(xb + reflect_idx(gbase + off + 512));
                X2[jj] = __ldg(xb + reflect_idx(gbase + off + 1024));
            }
#pragma unroll
            for (int jj = 0; jj < 8; ++jj) {
                const int j = 8 * half8 + jj;
                const float wm = 0.5f - 0.5f * wcc;
                const float wp = 0.5f + 0.5f * wcc;
                const float z0r = wm * X0[jj], z0i = wm * X1[jj];
                const float z1r = wp * X1[jj], z1i = wp * X2[jj];
                if (h == 0) {                      // u = z0 + z1
                    ar[j] = z0r + z1r;
                    ai[j] = z0i + z1i;
                } else {                           // v = (z0 - z1) * W32^j
                    const float dr = z0r - z1r;
                    const float di = z0i - z1i;
                    ar[j] = dr * C32c[j] + di * S32c[j];
                    ai[j] = di * C32c[j] - dr * S32c[j];
                }
                const float nc = wcc * Cs - wss * Ss;
                wss = wss * Cs + wcc * Ss;
                wcc = nc;
            }
        }
        fft16(ar, ai);     // reg r holds A[n2, k1 = 2*brev4(r) + h]

        // ---- twiddle by W1024^{n2*k1}, k1 = 2m + h, m = 4q + p.
        // Seeds W^{n2*(2p+h)} from one sincospif by complex squaring; step W^8n2.
        float w2r, w2i, w4r, w4i, w6r, w6i, w8r, w8i;
        cmul(w2r, w2i, c0, -s0, c0, -s0);          // W^2n2
        cmul(w4r, w4i, w2r, w2i, w2r, w2i);        // W^4n2
        cmul(w6r, w6i, w2r, w2i, w4r, w4i);        // W^6n2
        cmul(w8r, w8i, w4r, w4i, w4r, w4i);        // W^8n2
        const float br = h ? c0 : 1.0f;
        const float bi = h ? -s0 : 0.0f;
        float cr[4], ci[4];
        cr[0] = br;  ci[0] = bi;
        cmul(cr[1], ci[1], br, bi, w2r, w2i);
        cmul(cr[2], ci[2], br, bi, w4r, w4i);
        cmul(cr[3], ci[3], br, bi, w6r, w6i);

#pragma unroll
        for (int q = 0; q < 4; ++q) {
#pragma unroll
            for (int p = 0; p < 4; ++p) {
                const int m  = 4 * q + p;
                const int r  = brev4(m);
                const int k1 = 2 * m + h;
                float vr, vi;
                cmul(vr, vi, ar[r], ai[r], cr[p], ci[p]);
                tile[k1 * TSTRIDE + n2] = make_float2(vr, vi);   // STS.64
                if (q < 3) {
                    float nr, ni;
                    cmul(nr, ni, cr[p], ci[p], w8r, w8i);
                    cr[p] = nr; ci[p] = ni;
                }
            }
        }

        // group barrier: tile stores -> tile loads (2 warps, id grp+1)
        asm volatile("bar.sync %0, %1;" :: "r"(grp + 1), "r"(64) : "memory");

        // ---- stage B: k1 -> lane map keeps k1 and 32-k1 in the SAME warp.
        int k1;
        if (wsub == 0) {
            if (l4 == 0)      k1 = 0;
            else if (l4 == 1) k1 = 16;
            else {
                const int p = l4 >> 1;
                k1 = (l4 & 1) ? (32 - p) : p;
            }
        } else {
            const int p = 8 + (l4 >> 1);
            k1 = (l4 & 1) ? (32 - p) : p;
        }

        // vectorized dual-half reads (LDS.128) + local cross butterfly.
        const float4* t4lo = (const float4*)(tile + k1 * TSTRIDE);       // n2v 0..15
        const float4* t4hi = (const float4*)(tile + k1 * TSTRIDE + 16);  // n2v 16..31
#pragma unroll
        for (int jq = 0; jq < 8; ++jq) {
            const float4 a0 = t4lo[jq];      // (z[2jq].re,.im, z[2jq+1].re,.im)
            const float4 a1 = t4hi[jq];
            const int j0 = 2 * jq, j1 = 2 * jq + 1;
            if (h == 0) {                    // u = a0 + a1
                ar[j0] = a0.x + a1.x;  ai[j0] = a0.y + a1.y;
                ar[j1] = a0.z + a1.z;  ai[j1] = a0.w + a1.w;
            } else {                         // v = (a0 - a1) * W32^j
                float dr = a0.x - a1.x, di = a0.y - a1.y;
                ar[j0] = dr * C32c[j0] + di * S32c[j0];
                ai[j0] = di * C32c[j0] - dr * S32c[j0];
                dr = a0.z - a1.z;  di = a0.w - a1.w;
                ar[j1] = dr * C32c[j1] + di * S32c[j1];
                ai[j1] = di * C32c[j1] - dr * S32c[j1];
            }
        }
        fft16(ar, ai);     // reg r holds Z[k1 + 32*(2*brev4(r) + h)]

        // group barrier: tile reads done -> magG (union) may be overwritten
        asm volatile("bar.sync %0, %1;" :: "r"(grp + 1), "r"(64) : "memory");

        // ---- conjugate-symmetry unpack + magnitudes.
        // partner of even reg r at reg 15-r of: generic lane^17; k1==16 lane^16
        // (warp0,l4==1); k1==0 same lane (warp0,l4==0; h==0 via TBL).
        const bool k1zero = (wsub == 0) && (l4 == 0);
        const bool k1mid  = (wsub == 0) && (l4 == 1);
        const int msk = k1zero ? 0 : (k1mid ? 16 : 17);
        constexpr int TBL[8] = { 0, 3, 7, 5, 15, 13, 11, 9 };
        float qr_[8], qi_[8];
#pragma unroll
        for (int ri = 0; ri < 8; ++ri) {        // batch all unpack shuffles
            qr_[ri] = __shfl_xor_sync(FULLMASK, ar[15 - 2 * ri], msk);
            qi_[ri] = __shfl_xor_sync(FULLMASK, ai[15 - 2 * ri], msk);
        }
#pragma unroll
        for (int ri = 0; ri < 8; ++ri) {
            const int r = 2 * ri;
            float qr = qr_[ri], qi = qi_[ri];
            if (k1zero && h == 0) { qr = ar[TBL[ri]]; qi = ai[TBL[ri]]; }
            const float zr = ar[r], zi = ai[r];
            const float e0r = zr + qr, e0i = zi - qi;   // X_t[k]     * 2
            const float e1r = zr - qr, e1i = zi + qi;   // X_{t+1}[k] * 2i
            const float m0 = 0.5f * sqrt_fast(e0r * e0r + e0i * e0i);
            const float m1 = 0.5f * sqrt_fast(e1r * e1r + e1i * e1i);
            const int k2 = 2 * brev4(r) + h;
            const int k  = k1 + 32 * k2;
            magG[k] = make_float2(m0, m1);              // STS.64 into union
        }
        if (k1zero && h == 0) {   // k = 512 lives at reg 1 (k2 = 16)
            magG[512] = make_float2(fabsf(ar[1]), fabsf(ai[1]));
        }
    }
    __syncthreads();

    // ---- writeback: thread -> (k, group); LDS.64 then two STG.32
    const size_t obase = (size_t)b * CUTOFF * NFRAMES;
    for (int i = tid; i < CUTOFF * NGROUP; i += THREADS) {   // 513*4 = 2052
        const int k = i >> 2;
        const int g = i & 3;
        const float2 v = sm2[g * GSTRIDE + k];
        const int tt = t0 + 2 * g;
        float* orow = out + obase + (size_t)k * NFRAMES;
        if (tt < NFRAMES)     orow[tt] = v.x;
        if (tt + 1 < NFRAMES) orow[tt + 1] = v.y;
    }
}

extern "C" void kernel_launch(void* const* d_in, const int* in_sizes, int n_in,
                              void* d_out, int out_size) {
    const float* x = (const float*)d_in[0];
    // d_in[1] = forward_basis: identical to our windowed DFT; unused.
    float* out = (float*)d_out;

    cudaFuncSetAttribute(stft_kernel,
                         cudaFuncAttributeMaxDynamicSharedMemorySize, SMEM_BYTES);

    dim3 grid((NFRAMES + FPB - 1) / FPB, BATCHES);
    stft_kernel<<<grid, THREADS, SMEM_BYTES>>>(x, out);
}

// round 12
// speedup vs baseline: 2.7946x; 2.2633x over previous
#include <cuda_runtime.h>
#include <cstddef>

// STFT via four-step FFT (1024 = 32x32), real-pair packed, 2 lanes per 32-pt FFT.
// Round-12: f32x2 PACKED butterflies (fma.rn.f32x2) — consecutive-j pairs share
// one packed register; fft16 stages 1-3 and the stage-B cross butterfly run at
// 2 fp32 ops per issue slot. Stage 4 (intra-pair, twiddle-free) is the unpack.
//
// Output: magnitude (32, 513, 1025) fp32.

#define NS        524288
#define BATCHES   32
#define NFRAMES   1025
#define CUTOFF    513
#define HOP       512
#define FPB       8         // frames per block (4 groups x 2 frames)
#define THREADS   256
#define NGROUP    4
#define FULLMASK  0xFFFFFFFFu

#define TSTRIDE   34
#define TILE_F2   (32*TSTRIDE)                  // 1088 float2
#define GSTRIDE   (TILE_F2 + 8)                 // 1096 float2
#define SM_F2     (NGROUP * GSTRIDE)            // 4384
#define SMEM_BYTES (SM_F2 * 8)                  // 35072 B

typedef unsigned long long u64;

__device__ __forceinline__ u64 pk2(float lo, float hi) {
    u64 r; asm("mov.b64 %0, {%1, %2};" : "=l"(r) : "f"(lo), "f"(hi)); return r;
}
__device__ __forceinline__ void upk2(float& lo, float& hi, u64 v) {
    asm("mov.b64 {%0, %1}, %2;" : "=f"(lo), "=f"(hi) : "l"(v));
}
__device__ __forceinline__ u64 add2(u64 a, u64 b) {
    u64 r; asm("add.rn.f32x2 %0, %1, %2;" : "=l"(r) : "l"(a), "l"(b)); return r;
}
__device__ __forceinline__ u64 mul2(u64 a, u64 b) {
    u64 r; asm("mul.rn.f32x2 %0, %1, %2;" : "=l"(r) : "l"(a), "l"(b)); return r;
}
__device__ __forceinline__ u64 fma2(u64 a, u64 b, u64 c) {
    u64 r; asm("fma.rn.f32x2 %0, %1, %2, %3;" : "=l"(r) : "l"(a), "l"(b), "l"(c)); return r;
}

__device__ __forceinline__ constexpr int brev4(int x) {
    return ((x & 1) << 3) | ((x & 2) << 1) | ((x & 4) >> 1) | ((x & 8) >> 3);
}

__device__ __forceinline__ float sqrt_fast(float x) {
    float r;
    asm("sqrt.approx.f32 %0, %1;" : "=f"(r) : "f"(x));
    return r;
}

__device__ __forceinline__ void cmul(float& dr, float& di,
                                     float ar, float ai, float br, float bi) {
    dr = ar * br - ai * bi;
    di = ar * bi + ai * br;
}

// 16-pt tables: c = TC8[m] = cos(2pi m/16), s = TS8[m] = sin(2pi m/16)
#define TC8_0 1.0f
#define TC8_1 0.9238795325f
#define TC8_2 0.7071067812f
#define TC8_3 0.3826834324f
#define TC8_4 0.0f
#define TC8_5 (-0.3826834324f)
#define TC8_6 (-0.7071067812f)
#define TC8_7 (-0.9238795325f)
#define TS8_0 0.0f
#define TS8_1 0.3826834324f
#define TS8_2 0.7071067812f
#define TS8_3 0.9238795325f
#define TS8_4 1.0f
#define TS8_5 0.9238795325f
#define TS8_6 0.7071067812f
#define TS8_7 0.3826834324f

// W32^j = C32[j] - i*S32[j]
__device__ __constant__ const float C32c[16] = {
    1.0f, 0.9807852804f, 0.9238795325f, 0.8314696123f,
    0.7071067812f, 0.5555702330f, 0.3826834324f, 0.1950903220f,
    0.0f, -0.1950903220f, -0.3826834324f, -0.5555702330f,
    -0.7071067812f, -0.8314696123f, -0.9238795325f, -0.9807852804f };
__device__ __constant__ const float S32c[16] = {
    0.0f, 0.1950903220f, 0.3826834324f, 0.5555702330f,
    0.7071067812f, 0.8314696123f, 0.9238795325f, 0.9807852804f,
    1.0f, 0.9807852804f, 0.9238795325f, 0.8314696123f,
    0.7071067812f, 0.5555702330f, 0.3826834324f, 0.1950903220f };

// Packed butterfly: (p, q) pair indices; twiddle applied to the q output.
#define PBFLY(AR, AI, P, Q, C2, S2, NS2, NEG1)                      \
    {   const u64 ur_ = add2(AR[P], AR[Q]);                         \
        const u64 ui_ = add2(AI[P], AI[Q]);                         \
        const u64 vr_ = fma2(AR[Q], NEG1, AR[P]);                   \
        const u64 vi_ = fma2(AI[Q], NEG1, AI[P]);                   \
        AR[P] = ur_; AI[P] = ui_;                                   \
        AR[Q] = fma2(vi_, S2, mul2(vr_, C2));                       \
        AI[Q] = fma2(vr_, NS2, mul2(vi_, C2)); }

// Packed DIF 16-pt FFT. Input: ar2[p] = (x[2p], x[2p+1]). Output scalar,
// bit-reversed: ar[r] = X[brev4(r)] (identical math to the scalar version).
__device__ __forceinline__ void fft16p(u64 ar2[8], u64 ai2[8],
                                       float ar[16], float ai[16]) {
    const u64 NEG1 = pk2(-1.0f, -1.0f);
    // stage 1 (half=8): pairs (p, p+4); c = TC8[j], j = 2p, 2p+1
    {
        const u64 c0 = pk2(TC8_0, TC8_1), s0 = pk2(TS8_0, TS8_1), n0 = pk2(-TS8_0, -TS8_1);
        const u64 c1 = pk2(TC8_2, TC8_3), s1 = pk2(TS8_2, TS8_3), n1 = pk2(-TS8_2, -TS8_3);
        const u64 c2 = pk2(TC8_4, TC8_5), s2 = pk2(TS8_4, TS8_5), n2 = pk2(-TS8_4, -TS8_5);
        const u64 c3 = pk2(TC8_6, TC8_7), s3 = pk2(TS8_6, TS8_7), n3 = pk2(-TS8_6, -TS8_7);
        PBFLY(ar2, ai2, 0, 4, c0, s0, n0, NEG1);
        PBFLY(ar2, ai2, 1, 5, c1, s1, n1, NEG1);
        PBFLY(ar2, ai2, 2, 6, c2, s2, n2, NEG1);
        PBFLY(ar2, ai2, 3, 7, c3, s3, n3, NEG1);
    }
    // stage 2 (half=4): blocks {0,4}; pairs (b+jp, b+jp+2); c = TC8[2j]:
    // jp=0 -> (TC8[0], TC8[2]); jp=1 -> (TC8[4], TC8[6])
    {
        const u64 c0 = pk2(TC8_0, TC8_2), s0 = pk2(TS8_0, TS8_2), n0 = pk2(-TS8_0, -TS8_2);
        const u64 c1 = pk2(TC8_4, TC8_6), s1 = pk2(TS8_4, TS8_6), n1 = pk2(-TS8_4, -TS8_6);
        PBFLY(ar2, ai2, 0, 2, c0, s0, n0, NEG1);
        PBFLY(ar2, ai2, 1, 3, c1, s1, n1, NEG1);
        PBFLY(ar2, ai2, 4, 6, c0, s0, n0, NEG1);
        PBFLY(ar2, ai2, 5, 7, c1, s1, n1, NEG1);
    }
    // stage 3 (half=2): pairs (2b, 2b+1); c = (TC8[0], TC8[4]) = (1,0), s = (0,1)
    {
        const u64 c0 = pk2(1.0f, 0.0f), s0 = pk2(0.0f, 1.0f), n0 = pk2(0.0f, -1.0f);
        PBFLY(ar2, ai2, 0, 1, c0, s0, n0, NEG1);
        PBFLY(ar2, ai2, 2, 3, c0, s0, n0, NEG1);
        PBFLY(ar2, ai2, 4, 5, c0, s0, n0, NEG1);
        PBFLY(ar2, ai2, 6, 7, c0, s0, n0, NEG1);
    }
    // stage 4 (half=1, twiddle-free): intra-pair scalar butterfly = unpack
#pragma unroll
    for (int p = 0; p < 8; ++p) {
        float x0, x1, y0, y1;
        upk2(x0, x1, ar2[p]);
        upk2(y0, y1, ai2[p]);
        ar[2 * p] = x0 + x1;  ar[2 * p + 1] = x0 - x1;
        ai[2 * p] = y0 + y1;  ai[2 * p + 1] = y0 - y1;
    }
}

__device__ __forceinline__ int reflect_idx(int idx) {
    idx = (idx < 0) ? -idx : idx;
    idx = (idx >= NS) ? (2 * NS - 2 - idx) : idx;
    return idx;
}

__global__ void __launch_bounds__(THREADS, 3)
stft_kernel(const float* __restrict__ x, float* __restrict__ out) {
    extern __shared__ float2 sm2[];

    const int tid  = threadIdx.x;
    const int warp = tid >> 5;
    const int lane = tid & 31;
    const int l4   = lane & 15;
    const int h    = lane >> 4;          // half-bit within the lane pair
    const int grp  = warp >> 1;          // 2-warp group = one frame pair
    const int wsub = warp & 1;
    float2* tile = sm2 + grp * GSTRIDE;
    float2* magG = tile;                 // UNION: tile dead after stage-B reads

    const int b  = blockIdx.y;
    const int t0 = blockIdx.x * FPB;
    const float* __restrict__ xb = x + (size_t)b * NS;

    const int t = t0 + grp * 2;
    const bool active = (t < NFRAMES);

    float ar[16], ai[16];
    u64 ar2[8], ai2[8];
    const int n2 = l4 + 16 * wsub;

    // One trig call per lane: c0 = cos(pi*n2/512), s0 = sin(pi*n2/512)
    float s0, c0;
    sincospif((float)n2 * (1.0f / 512.0f), &s0, &c0);

    if (active) {
        // ---- stage A: cross butterfly straight from overlapping loads.
        // z[n] = w[n]*(X[n] + i*X[n+512]); partner z[n+512] = w[n+512]*(X[n+512]+i*X[n+1024]).
        const int gbase = t * HOP - 512 + n2;
        const float Cs = 0.9807852804f, Ss = 0.1950903220f;  // rot by pi/16
        float wcc = c0, wss = s0;
#pragma unroll
        for (int half8 = 0; half8 < 2; ++half8) {
            float X0[8], X1[8], X2[8];
#pragma unroll
            for (int jj = 0; jj < 8; ++jj) {
                const int off = 32 * (8 * half8 + jj);
                X0[jj] = __ldg(xb + reflect_idx(gbase + off));
                X1[jj] = __ldg(xb + reflect_idx(gbase + off + 512));
                X2[jj] = __ldg(xb + reflect_idx(gbase + off + 1024));
            }
#pragma unroll
            for (int jj = 0; jj < 8; ++jj) {
                const int j = 8 * half8 + jj;
                const float wm = 0.5f - 0.5f * wcc;
                const float wp = 0.5f + 0.5f * wcc;
                const float z0r = wm * X0[jj], z0i = wm * X1[jj];
                const float z1r = wp * X1[jj], z1i = wp * X2[jj];
                if (h == 0) {                      // u = z0 + z1
                    ar[j] = z0r + z1r;
                    ai[j] = z0i + z1i;
                } else {                           // v = (z0 - z1) * W32^j
                    const float dr = z0r - z1r;
                    const float di = z0i - z1i;
                    ar[j] = dr * C32c[j] + di * S32c[j];
                    ai[j] = di * C32c[j] - dr * S32c[j];
                }
                const float nc = wcc * Cs - wss * Ss;
                wss = wss * Cs + wcc * Ss;
                wcc = nc;
            }
        }
        // pack and run the packed FFT
#pragma unroll
        for (int p = 0; p < 8; ++p) {
            ar2[p] = pk2(ar[2 * p], ar[2 * p + 1]);
            ai2[p] = pk2(ai[2 * p], ai[2 * p + 1]);
        }
        fft16p(ar2, ai2, ar, ai);   // reg r holds A[n2, k1 = 2*brev4(r) + h]

        // ---- twiddle by W1024^{n2*k1}, k1 = 2m + h, m = 4q + p.
        float w2r, w2i, w4r, w4i, w6r, w6i, w8r, w8i;
        cmul(w2r, w2i, c0, -s0, c0, -s0);          // W^2n2
        cmul(w4r, w4i, w2r, w2i, w2r, w2i);        // W^4n2
        cmul(w6r, w6i, w2r, w2i, w4r, w4i);        // W^6n2
        cmul(w8r, w8i, w4r, w4i, w4r, w4i);        // W^8n2
        const float br = h ? c0 : 1.0f;
        const float bi = h ? -s0 : 0.0f;
        float cr[4], ci[4];
        cr[0] = br;  ci[0] = bi;
        cmul(cr[1], ci[1], br, bi, w2r, w2i);
        cmul(cr[2], ci[2], br, bi, w4r, w4i);
        cmul(cr[3], ci[3], br, bi, w6r, w6i);

#pragma unroll
        for (int q = 0; q < 4; ++q) {
#pragma unroll
            for (int p = 0; p < 4; ++p) {
                const int m  = 4 * q + p;
                const int r  = brev4(m);
                const int k1 = 2 * m + h;
                float vr, vi;
                cmul(vr, vi, ar[r], ai[r], cr[p], ci[p]);
                tile[k1 * TSTRIDE + n2] = make_float2(vr, vi);   // STS.64
                if (q < 3) {
                    float nr, ni;
                    cmul(nr, ni, cr[p], ci[p], w8r, w8i);
                    cr[p] = nr; ci[p] = ni;
                }
            }
        }

        // group barrier: tile stores -> tile loads (2 warps, id grp+1)
        asm volatile("bar.sync %0, %1;" :: "r"(grp + 1), "r"(64) : "memory");

        // ---- stage B: k1 -> lane map keeps k1 and 32-k1 in the SAME warp.
        int k1;
        if (wsub == 0) {
            if (l4 == 0)      k1 = 0;
            else if (l4 == 1) k1 = 16;
            else {
                const int p = l4 >> 1;
                k1 = (l4 & 1) ? (32 - p) : p;
            }
        } else {
            const int p = 8 + (l4 >> 1);
            k1 = (l4 & 1) ? (32 - p) : p;
        }

        // vectorized dual-half reads (LDS.128) + PACKED cross butterfly.
        const float4* t4lo = (const float4*)(tile + k1 * TSTRIDE);       // n2v 0..15
        const float4* t4hi = (const float4*)(tile + k1 * TSTRIDE + 16);  // n2v 16..31
        const u64 NEG1 = pk2(-1.0f, -1.0f);
#pragma unroll
        for (int jq = 0; jq < 8; ++jq) {
            const float4 a0 = t4lo[jq];      // (z[2jq].re, .im, z[2jq+1].re, .im)
            const float4 a1 = t4hi[jq];
            const u64 r0 = pk2(a0.x, a0.z), i0 = pk2(a0.y, a0.w);
            const u64 r1 = pk2(a1.x, a1.z), i1 = pk2(a1.y, a1.w);
            if (h == 0) {                    // u = a0 + a1
                ar2[jq] = add2(r0, r1);
                ai2[jq] = add2(i0, i1);
            } else {                         // v = (a0 - a1) * W32^j
                const u64 vr = fma2(r1, NEG1, r0);
                const u64 vi = fma2(i1, NEG1, i0);
                const int j0 = 2 * jq, j1 = 2 * jq + 1;
                const u64 c2  = pk2(C32c[j0], C32c[j1]);
                const u64 s2  = pk2(S32c[j0], S32c[j1]);
                const u64 ns2 = pk2(-S32c[j0], -S32c[j1]);
                ar2[jq] = fma2(vi, s2, mul2(vr, c2));
                ai2[jq] = fma2(vr, ns2, mul2(vi, c2));
            }
        }
        fft16p(ar2, ai2, ar, ai);   // reg r holds Z[k1 + 32*(2*brev4(r) + h)]

        // group barrier: tile reads done -> magG (union) may be overwritten
        asm volatile("bar.sync %0, %1;" :: "r"(grp + 1), "r"(64) : "memory");

        // ---- conjugate-symmetry unpack + magnitudes.
        // partner of even reg r at reg 15-r of: generic lane^17; k1==16 lane^16
        // (warp0,l4==1); k1==0 same lane (warp0,l4==0; h==0 via TBL).
        const bool k1zero = (wsub == 0) && (l4 == 0);
        const bool k1mid  = (wsub == 0) && (l4 == 1);
        const int msk = k1zero ? 0 : (k1mid ? 16 : 17);
        constexpr int TBL[8] = { 0, 3, 7, 5, 15, 13, 11, 9 };
        float qr_[8], qi_[8];
#pragma unroll
        for (int ri = 0; ri < 8; ++ri) {        // batch all unpack shuffles
            qr_[ri] = __shfl_xor_sync(FULLMASK, ar[15 - 2 * ri], msk);
            qi_[ri] = __shfl_xor_sync(FULLMASK, ai[15 - 2 * ri], msk);
        }
#pragma unroll
        for (int ri = 0; ri < 8; ++ri) {
            const int r = 2 * ri;
            float qr = qr_[ri], qi = qi_[ri];
            if (k1zero && h == 0) { qr = ar[TBL[ri]]; qi = ai[TBL[ri]]; }
            const float zr = ar[r], zi = ai[r];
            const float e0r = zr + qr, e0i = zi - qi;   // X_t[k]     * 2
            const float e1r = zr - qr, e1i = zi + qi;   // X_{t+1}[k] * 2i
            const float m0 = 0.5f * sqrt_fast(e0r * e0r + e0i * e0i);
            const float m1 = 0.5f * sqrt_fast(e1r * e1r + e1i * e1i);
            const int k2 = 2 * brev4(r) + h;
            const int k  = k1 + 32 * k2;
            magG[k] = make_float2(m0, m1);              // STS.64 into union
        }
        if (k1zero && h == 0) {   // k = 512 lives at reg 1 (k2 = 16)
            magG[512] = make_float2(fabsf(ar[1]), fabsf(ai[1]));
        }
    }
    __syncthreads();

    // ---- writeback: thread -> (k, group); LDS.64 then two STG.32
    const size_t obase = (size_t)b * CUTOFF * NFRAMES;
    for (int i = tid; i < CUTOFF * NGROUP; i += THREADS) {   // 513*4 = 2052
        const int k = i >> 2;
        const int g = i & 3;
        const float2 v = sm2[g * GSTRIDE + k];
        const int tt = t0 + 2 * g;
        float* orow = out + obase + (size_t)k * NFRAMES;
        if (tt < NFRAMES)     orow[tt] = v.x;
        if (tt + 1 < NFRAMES) orow[tt + 1] = v.y;
    }
}

extern "C" void kernel_launch(void* const* d_in, const int* in_sizes, int n_in,
                              void* d_out, int out_size) {
    const float* x = (const float*)d_in[0];
    // d_in[1] = forward_basis: identical to our windowed DFT; unused.
    float* out = (float*)d_out;

    cudaFuncSetAttribute(stft_kernel,
                         cudaFuncAttributeMaxDynamicSharedMemorySize, SMEM_BYTES);

    dim3 grid((NFRAMES + FPB - 1) / FPB, BATCHES);
    stft_kernel<<<grid, THREADS, SMEM_BYTES>>>(x, out);
}

// round 14
// speedup vs baseline: 2.9621x; 1.0599x over previous
#include <cuda_runtime.h>
#include <cstddef>

// STFT via four-step FFT (1024 = 32x32), real-pair packed, 2 lanes per 32-pt FFT.
// Round-14 (= R13 fixed): issue-slot diet. Interior blocks skip reflect entirely;
// stage A fully f32x2-packed; __sincosf; __device__ constexpr twiddle tables
// (immediates, no LDC); writeback predicates hoisted to the last block only.
//
// Output: magnitude (32, 513, 1025) fp32.

#define NS        524288
#define BATCHES   32
#define NFRAMES   1025
#define CUTOFF    513
#define HOP       512
#define FPB       8         // frames per block (4 groups x 2 frames)
#define THREADS   256
#define NGROUP    4
#define FULLMASK  0xFFFFFFFFu

#define TSTRIDE   34
#define TILE_F2   (32*TSTRIDE)                  // 1088 float2
#define GSTRIDE   (TILE_F2 + 8)                 // 1096 float2
#define SM_F2     (NGROUP * GSTRIDE)            // 4384
#define SMEM_BYTES (SM_F2 * 8)                  // 35072 B

typedef unsigned long long u64;

__device__ __forceinline__ u64 pk2(float lo, float hi) {
    u64 r; asm("mov.b64 %0, {%1, %2};" : "=l"(r) : "f"(lo), "f"(hi)); return r;
}
__device__ __forceinline__ void upk2(float& lo, float& hi, u64 v) {
    asm("mov.b64 {%0, %1}, %2;" : "=f"(lo), "=f"(hi) : "l"(v));
}
__device__ __forceinline__ u64 add2(u64 a, u64 b) {
    u64 r; asm("add.rn.f32x2 %0, %1, %2;" : "=l"(r) : "l"(a), "l"(b)); return r;
}
__device__ __forceinline__ u64 mul2(u64 a, u64 b) {
    u64 r; asm("mul.rn.f32x2 %0, %1, %2;" : "=l"(r) : "l"(a), "l"(b)); return r;
}
__device__ __forceinline__ u64 fma2(u64 a, u64 b, u64 c) {
    u64 r; asm("fma.rn.f32x2 %0, %1, %2, %3;" : "=l"(r) : "l"(a), "l"(b), "l"(c)); return r;
}

__device__ __forceinline__ constexpr int brev4(int x) {
    return ((x & 1) << 3) | ((x & 2) << 1) | ((x & 4) >> 1) | ((x & 8) >> 3);
}

__device__ __forceinline__ float sqrt_fast(float x) {
    float r;
    asm("sqrt.approx.f32 %0, %1;" : "=f"(r) : "f"(x));
    return r;
}

__device__ __forceinline__ void cmul(float& dr, float& di,
                                     float ar, float ai, float br, float bi) {
    dr = ar * br - ai * bi;
    di = ar * bi + ai * br;
}

// 16-pt tables
#define TC8_0 1.0f
#define TC8_1 0.9238795325f
#define TC8_2 0.7071067812f
#define TC8_3 0.3826834324f
#define TC8_4 0.0f
#define TC8_5 (-0.3826834324f)
#define TC8_6 (-0.7071067812f)
#define TC8_7 (-0.9238795325f)
#define TS8_0 0.0f
#define TS8_1 0.3826834324f
#define TS8_2 0.7071067812f
#define TS8_3 0.9238795325f
#define TS8_4 1.0f
#define TS8_5 0.9238795325f
#define TS8_6 0.7071067812f
#define TS8_7 0.3826834324f

// W32^j = C32[j] - i*S32[j] — __device__ constexpr: folds to immediates after
// unrolling, legal in device code (the R13 version lacked __device__).
__device__ constexpr float C32[16] = {
    1.0f, 0.9807852804f, 0.9238795325f, 0.8314696123f,
    0.7071067812f, 0.5555702330f, 0.3826834324f, 0.1950903220f,
    0.0f, -0.1950903220f, -0.3826834324f, -0.5555702330f,
    -0.7071067812f, -0.8314696123f, -0.9238795325f, -0.9807852804f };
__device__ constexpr float S32[16] = {
    0.0f, 0.1950903220f, 0.3826834324f, 0.5555702330f,
    0.7071067812f, 0.8314696123f, 0.9238795325f, 0.9807852804f,
    1.0f, 0.9807852804f, 0.9238795325f, 0.8314696123f,
    0.7071067812f, 0.5555702330f, 0.3826834324f, 0.1950903220f };

// Packed butterfly: (p, q) pair indices; twiddle applied to the q output.
#define PBFLY(AR, AI, P, Q, C2, S2, NS2, NEG1)                      \
    {   const u64 ur_ = add2(AR[P], AR[Q]);                         \
        const u64 ui_ = add2(AI[P], AI[Q]);                         \
        const u64 vr_ = fma2(AR[Q], NEG1, AR[P]);                   \
        const u64 vi_ = fma2(AI[Q], NEG1, AI[P]);                   \
        AR[P] = ur_; AI[P] = ui_;                                   \
        AR[Q] = fma2(vi_, S2, mul2(vr_, C2));                       \
        AI[Q] = fma2(vr_, NS2, mul2(vi_, C2)); }

// Packed DIF 16-pt FFT. Input: ar2[p] = (x[2p], x[2p+1]). Output scalar,
// bit-reversed: ar[r] = X[brev4(r)].
__device__ __forceinline__ void fft16p(u64 ar2[8], u64 ai2[8],
                                       float ar[16], float ai[16]) {
    const u64 NEG1 = pk2(-1.0f, -1.0f);
    {   // stage 1 (half=8)
        const u64 c0 = pk2(TC8_0, TC8_1), s0 = pk2(TS8_0, TS8_1), n0 = pk2(-TS8_0, -TS8_1);
        const u64 c1 = pk2(TC8_2, TC8_3), s1 = pk2(TS8_2, TS8_3), n1 = pk2(-TS8_2, -TS8_3);
        const u64 c2 = pk2(TC8_4, TC8_5), s2 = pk2(TS8_4, TS8_5), n2 = pk2(-TS8_4, -TS8_5);
        const u64 c3 = pk2(TC8_6, TC8_7), s3 = pk2(TS8_6, TS8_7), n3 = pk2(-TS8_6, -TS8_7);
        PBFLY(ar2, ai2, 0, 4, c0, s0, n0, NEG1);
        PBFLY(ar2, ai2, 1, 5, c1, s1, n1, NEG1);
        PBFLY(ar2, ai2, 2, 6, c2, s2, n2, NEG1);
        PBFLY(ar2, ai2, 3, 7, c3, s3, n3, NEG1);
    }
    {   // stage 2 (half=4)
        const u64 c0 = pk2(TC8_0, TC8_2), s0 = pk2(TS8_0, TS8_2), n0 = pk2(-TS8_0, -TS8_2);
        const u64 c1 = pk2(TC8_4, TC8_6), s1 = pk2(TS8_4, TS8_6), n1 = pk2(-TS8_4, -TS8_6);
        PBFLY(ar2, ai2, 0, 2, c0, s0, n0, NEG1);
        PBFLY(ar2, ai2, 1, 3, c1, s1, n1, NEG1);
        PBFLY(ar2, ai2, 4, 6, c0, s0, n0, NEG1);
        PBFLY(ar2, ai2, 5, 7, c1, s1, n1, NEG1);
    }
    {   // stage 3 (half=2)
        const u64 c0 = pk2(1.0f, 0.0f), s0 = pk2(0.0f, 1.0f), n0 = pk2(0.0f, -1.0f);
        PBFLY(ar2, ai2, 0, 1, c0, s0, n0, NEG1);
        PBFLY(ar2, ai2, 2, 3, c0, s0, n0, NEG1);
        PBFLY(ar2, ai2, 4, 5, c0, s0, n0, NEG1);
        PBFLY(ar2, ai2, 6, 7, c0, s0, n0, NEG1);
    }
    // stage 4 (half=1, twiddle-free): intra-pair scalar butterfly = unpack
#pragma unroll
    for (int p = 0; p < 8; ++p) {
        float x0, x1, y0, y1;
        upk2(x0, x1, ar2[p]);
        upk2(y0, y1, ai2[p]);
        ar[2 * p] = x0 + x1;  ar[2 * p + 1] = x0 - x1;
        ai[2 * p] = y0 + y1;  ai[2 * p + 1] = y0 - y1;
    }
}

__device__ __forceinline__ int reflect_idx(int idx) {
    idx = (idx < 0) ? -idx : idx;
    idx = (idx >= NS) ? (2 * NS - 2 - idx) : idx;
    return idx;
}

__global__ void __launch_bounds__(THREADS, 3)
stft_kernel(const float* __restrict__ x, float* __restrict__ out) {
    extern __shared__ float2 sm2[];

    const int tid  = threadIdx.x;
    const int warp = tid >> 5;
    const int lane = tid & 31;
    const int l4   = lane & 15;
    const int h    = lane >> 4;          // half-bit within the lane pair
    const int grp  = warp >> 1;          // 2-warp group = one frame pair
    const int wsub = warp & 1;
    float2* tile = sm2 + grp * GSTRIDE;
    float2* magG = tile;                 // UNION: tile dead after stage-B reads

    const int b  = blockIdx.y;
    const int t0 = blockIdx.x * FPB;
    const float* __restrict__ xb = x + (size_t)b * NS;

    const int t = t0 + grp * 2;
    const bool active = (t < NFRAMES);
    // interior blocks never touch pad regions (x=1..gridDim.x-2 verified exact)
    const bool interior = (blockIdx.x != 0) && (blockIdx.x != gridDim.x - 1);

    float ar[16], ai[16];
    u64 ar2[8], ai2[8];
    const int n2 = l4 + 16 * wsub;

    // c0 = cos(pi*n2/512), s0 = sin(pi*n2/512) — MUFU fast path (arg <= 0.19)
    float s0, c0;
    __sincosf((float)n2 * 0.00613592315f, &s0, &c0);

    if (active) {
        // ---- stage A, fully packed over j-pairs (j = 2jp, 2jp+1).
        // z[n] = w[n]*(X[n] + i*X[n+512]); partner z[n+512] = w[n+512]*(X[n+512]+i*X[n+1024]).
        // h=0 keeps u = z0+z1; h=1 keeps v = (z0-z1)*W32^j.
        const int gbase = t * HOP - 512 + n2;
        const float Cs = 0.9807852804f, Ss = 0.1950903220f;   // rot pi/16
        // packed window cos/sin at angles (a + 2jp*pi/16, a + (2jp+1)*pi/16)
        u64 wcc2 = pk2(c0, c0 * Cs - s0 * Ss);
        u64 wss2 = pk2(s0, s0 * Cs + c0 * Ss);
        const u64 CS8  = pk2(0.9238795325f, 0.9238795325f);   // cos(pi/8)
        const u64 SS8  = pk2(0.3826834324f, 0.3826834324f);
        const u64 NSS8 = pk2(-0.3826834324f, -0.3826834324f);
        const u64 HALF = pk2(0.5f, 0.5f), NHALF = pk2(-0.5f, -0.5f);
        const u64 NEG1 = pk2(-1.0f, -1.0f);

#pragma unroll
        for (int c4 = 0; c4 < 2; ++c4) {
            u64 X0p[4], X1p[4], X2p[4];
            if (interior) {
#pragma unroll
                for (int jj = 0; jj < 4; ++jj) {
                    const int off = gbase + 64 * (4 * c4 + jj);
                    X0p[jj] = pk2(__ldg(xb + off),        __ldg(xb + off + 32));
                    X1p[jj] = pk2(__ldg(xb + off + 512),  __ldg(xb + off + 544));
                    X2p[jj] = pk2(__ldg(xb + off + 1024), __ldg(xb + off + 1056));
                }
            } else {
#pragma unroll
                for (int jj = 0; jj < 4; ++jj) {
                    const int off = gbase + 64 * (4 * c4 + jj);
                    X0p[jj] = pk2(__ldg(xb + reflect_idx(off)),
                                  __ldg(xb + reflect_idx(off + 32)));
                    X1p[jj] = pk2(__ldg(xb + reflect_idx(off + 512)),
                                  __ldg(xb + reflect_idx(off + 544)));
                    X2p[jj] = pk2(__ldg(xb + reflect_idx(off + 1024)),
                                  __ldg(xb + reflect_idx(off + 1056)));
                }
            }
#pragma unroll
            for (int jj = 0; jj < 4; ++jj) {
                const int jp = 4 * c4 + jj;
                const int j0 = 2 * jp, j1 = j0 + 1;
                const u64 wm2 = fma2(wcc2, NHALF, HALF);   // 0.5 - 0.5*cos
                const u64 wp2 = fma2(wcc2, HALF, HALF);    // 0.5 + 0.5*cos
                const u64 z0r = mul2(wm2, X0p[jj]);
                const u64 z0i = mul2(wm2, X1p[jj]);
                const u64 z1r = mul2(wp2, X1p[jj]);
                const u64 z1i = mul2(wp2, X2p[jj]);
                if (h == 0) {
                    ar2[jp] = add2(z0r, z1r);
                    ai2[jp] = add2(z0i, z1i);
                } else {
                    const u64 vr = fma2(z1r, NEG1, z0r);
                    const u64 vi = fma2(z1i, NEG1, z0i);
                    const u64 c2  = pk2(C32[j0], C32[j1]);
                    const u64 s2  = pk2(S32[j0], S32[j1]);
                    const u64 ns2 = pk2(-S32[j0], -S32[j1]);
                    ar2[jp] = fma2(vi, s2, mul2(vr, c2));
                    ai2[jp] = fma2(vr, ns2, mul2(vi, c2));
                }
                // advance window angles by pi/8
                const u64 nc = fma2(wss2, NSS8, mul2(wcc2, CS8));
                wss2 = fma2(wcc2, SS8, mul2(wss2, CS8));
                wcc2 = nc;
            }
        }
        fft16p(ar2, ai2, ar, ai);   // reg r holds A[n2, k1 = 2*brev4(r) + h]

        // ---- twiddle by W1024^{n2*k1}, k1 = 2m + h, m = 4q + p.
        float w2r, w2i, w4r, w4i, w6r, w6i, w8r, w8i;
        cmul(w2r, w2i, c0, -s0, c0, -s0);          // W^2n2
        cmul(w4r, w4i, w2r, w2i, w2r, w2i);        // W^4n2
        cmul(w6r, w6i, w2r, w2i, w4r, w4i);        // W^6n2
        cmul(w8r, w8i, w4r, w4i, w4r, w4i);        // W^8n2
        const float br = h ? c0 : 1.0f;
        const float bi = h ? -s0 : 0.0f;
        float cr[4], ci[4];
        cr[0] = br;  ci[0] = bi;
        cmul(cr[1], ci[1], br, bi, w2r, w2i);
        cmul(cr[2], ci[2], br, bi, w4r, w4i);
        cmul(cr[3], ci[3], br, bi, w6r, w6i);

#pragma unroll
        for (int q = 0; q < 4; ++q) {
#pragma unroll
            for (int p = 0; p < 4; ++p) {
                const int m  = 4 * q + p;
                const int r  = brev4(m);
                const int k1 = 2 * m + h;
                float vr, vi;
                cmul(vr, vi, ar[r], ai[r], cr[p], ci[p]);
                tile[k1 * TSTRIDE + n2] = make_float2(vr, vi);   // STS.64
                if (q < 3) {
                    float nr, ni;
                    cmul(nr, ni, cr[p], ci[p], w8r, w8i);
                    cr[p] = nr; ci[p] = ni;
                }
            }
        }

        // group barrier: tile stores -> tile loads (2 warps, id grp+1)
        asm volatile("bar.sync %0, %1;" :: "r"(grp + 1), "r"(64) : "memory");

        // ---- stage B: k1 -> lane map keeps k1 and 32-k1 in the SAME warp.
        int k1;
        if (wsub == 0) {
            if (l4 == 0)      k1 = 0;
            else if (l4 == 1) k1 = 16;
            else {
                const int p = l4 >> 1;
                k1 = (l4 & 1) ? (32 - p) : p;
            }
        } else {
            const int p = 8 + (l4 >> 1);
            k1 = (l4 & 1) ? (32 - p) : p;
        }

        // vectorized dual-half reads (LDS.128) + PACKED cross butterfly.
        const float4* t4lo = (const float4*)(tile + k1 * TSTRIDE);       // n2v 0..15
        const float4* t4hi = (const float4*)(tile + k1 * TSTRIDE + 16);  // n2v 16..31
        const u64 NEG1b = pk2(-1.0f, -1.0f);
#pragma unroll
        for (int jq = 0; jq < 8; ++jq) {
            const float4 a0 = t4lo[jq];      // (z[2jq].re, .im, z[2jq+1].re, .im)
            const float4 a1 = t4hi[jq];
            const u64 r0 = pk2(a0.x, a0.z), i0 = pk2(a0.y, a0.w);
            const u64 r1 = pk2(a1.x, a1.z), i1 = pk2(a1.y, a1.w);
            if (h == 0) {                    // u = a0 + a1
                ar2[jq] = add2(r0, r1);
                ai2[jq] = add2(i0, i1);
            } else {                         // v = (a0 - a1) * W32^j
                const u64 vr = fma2(r1, NEG1b, r0);
                const u64 vi = fma2(i1, NEG1b, i0);
                const int j0 = 2 * jq, j1 = 2 * jq + 1;
                const u64 c2  = pk2(C32[j0], C32[j1]);
                const u64 s2  = pk2(S32[j0], S32[j1]);
                const u64 ns2 = pk2(-S32[j0], -S32[j1]);
                ar2[jq] = fma2(vi, s2, mul2(vr, c2));
                ai2[jq] = fma2(vr, ns2, mul2(vi, c2));
            }
        }
        fft16p(ar2, ai2, ar, ai);   // reg r holds Z[k1 + 32*(2*brev4(r) + h)]

        // group barrier: tile reads done -> magG (union) may be overwritten
        asm volatile("bar.sync %0, %1;" :: "r"(grp + 1), "r"(64) : "memory");

        // ---- conjugate-symmetry unpack + magnitudes.
        const bool k1zero = (wsub == 0) && (l4 == 0);
        const bool k1mid  = (wsub == 0) && (l4 == 1);
        const int msk = k1zero ? 0 : (k1mid ? 16 : 17);
        constexpr int TBL[8] = { 0, 3, 7, 5, 15, 13, 11, 9 };
        float qr_[8], qi_[8];
#pragma unroll
        for (int ri = 0; ri < 8; ++ri) {        // batch all unpack shuffles
            qr_[ri] = __shfl_xor_sync(FULLMASK, ar[15 - 2 * ri], msk);
            qi_[ri] = __shfl_xor_sync(FULLMASK, ai[15 - 2 * ri], msk);
        }
#pragma unroll
        for (int ri = 0; ri < 8; ++ri) {
            const int r = 2 * ri;
            float qr = qr_[ri], qi = qi_[ri];
            if (k1zero && h == 0) { qr = ar[TBL[ri]]; qi = ai[TBL[ri]]; }
            const float zr = ar[r], zi = ai[r];
            const float e0r = zr + qr, e0i = zi - qi;   // X_t[k]     * 2
            const float e1r = zr - qr, e1i = zi + qi;   // X_{t+1}[k] * 2i
            const float m0 = 0.5f * sqrt_fast(e0r * e0r + e0i * e0i);
            const float m1 = 0.5f * sqrt_fast(e1r * e1r + e1i * e1i);
            const int k2 = 2 * brev4(r) + h;
            const int k  = k1 + 32 * k2;
            magG[k] = make_float2(m0, m1);              // STS.64 into union
        }
        if (k1zero && h == 0) {   // k = 512 lives at reg 1 (k2 = 16)
            magG[512] = make_float2(fabsf(ar[1]), fabsf(ai[1]));
        }
    }
    __syncthreads();

    // ---- writeback: thread -> (k, group); predicates only on the last block
    const size_t obase = (size_t)b * CUTOFF * NFRAMES;
    if (blockIdx.x != gridDim.x - 1) {
        for (int i = tid; i < CUTOFF * NGROUP; i += THREADS) {   // 513*4 = 2052
            const int k = i >> 2;
            const int g = i & 3;
            const float2 v = sm2[g * GSTRIDE + k];
            float* orow = out + obase + (size_t)k * NFRAMES + t0 + 2 * g;
            orow[0] = v.x;
            orow[1] = v.y;
        }
    } else {
        for (int i = tid; i < CUTOFF * NGROUP; i += THREADS) {
            const int k = i >> 2;
            const int g = i & 3;
            const float2 v = sm2[g * GSTRIDE + k];
            const int tt = t0 + 2 * g;
            float* orow = out + obase + (size_t)k * NFRAMES;
            if (tt < NFRAMES)     orow[tt] = v.x;
            if (tt + 1 < NFRAMES) orow[tt + 1] = v.y;
        }
    }
}

extern "C" void kernel_launch(void* const* d_in, const int* in_sizes, int n_in,
                              void* d_out, int out_size) {
    const float* x = (const float*)d_in[0];
    // d_in[1] = forward_basis: identical to our windowed DFT; unused.
    float* out = (float*)d_out;

    cudaFuncSetAttribute(stft_kernel,
                         cudaFuncAttributeMaxDynamicSharedMemorySize, SMEM_BYTES);

    dim3 grid((NFRAMES + FPB - 1) / FPB, BATCHES);
    stft_kernel<<<grid, THREADS, SMEM_BYTES>>>(x, out);
}